// round 1
// baseline (speedup 1.0000x reference)
#include <cuda_runtime.h>
#include <math.h>

#define DIM     512
#define NTOK    256
#define NB      2
#define NBLK    6
#define HEADS   8
#define DHEAD   64
#define DFF     1365
#define DFF2    2730
#define DFFP    1376        // DFF padded to multiple of 16
#define MAXM    42
#define ROWS    3072        // NBLK*NB*NTOK
#define RMS_EPS 1.1920929e-07f

// ---------------- scratch (device globals; no runtime allocation) ----------------
static __device__ float g_T   [ROWS * DIM];
static __device__ float g_XN  [ROWS * DIM];
static __device__ float g_Q   [ROWS * DIM];
static __device__ float g_KV  [ROWS * 1024];
static __device__ float g_O   [ROWS * DIM];
static __device__ float g_H   [ROWS * DFF2];
static __device__ float g_ACT [ROWS * DFFP];
static __device__ float g_Or  [ROWS * DIM];
static __device__ float g_msg [(size_t)MAXM * 512 * DIM];    // row = (m*2+b)*256+n
static __device__ float g_kvm [(size_t)MAXM * 512 * 1024];   // same row layout, 1024 cols
static __device__ float g_Wvp [DIM * DFFP];                  // padded ff_values_w

// ---------------- SGEMM:  Y[m,n] = sum_k X[m,k]*W[n,k] (+bias[n]) ----------------
// BM=128, BN=64, BK=16, 256 threads, each thread 8x4.
// Requirements: M % 128 == 0, K % 16 == 0, lda % 4 == 0, W row stride == K (%4==0).
__global__ __launch_bounds__(256) void sgemm_nt(
    const float* __restrict__ X, int lda,
    const float* __restrict__ W,
    const float* __restrict__ bias,
    float* __restrict__ Y,
    int M, int N, int K)
{
    __shared__ float As[16][132];
    __shared__ float Bs[16][68];

    const int tid  = threadIdx.x;
    const int bm0  = blockIdx.y * 128;
    const int bn0  = blockIdx.x * 64;
    const int trow = tid >> 4;   // 0..15 -> m offset trow*8
    const int tcol = tid & 15;   // 0..15 -> n offset tcol*4

    float acc[8][4];
#pragma unroll
    for (int i = 0; i < 8; i++)
#pragma unroll
        for (int j = 0; j < 4; j++) acc[i][j] = 0.0f;

    for (int k0 = 0; k0 < K; k0 += 16) {
        // X tile: 128x16 = 512 float4, 2 per thread
#pragma unroll
        for (int s = 0; s < 2; s++) {
            int u  = tid + s * 256;
            int r  = u >> 2;
            int c4 = u & 3;
            float4 v = *reinterpret_cast<const float4*>(
                X + (size_t)(bm0 + r) * lda + k0 + c4 * 4);
            As[c4 * 4 + 0][r] = v.x;
            As[c4 * 4 + 1][r] = v.y;
            As[c4 * 4 + 2][r] = v.z;
            As[c4 * 4 + 3][r] = v.w;
        }
        // W tile: 64x16 = 256 float4, 1 per thread (guard N)
        {
            int r  = tid >> 2;
            int c4 = tid & 3;
            float4 v = make_float4(0.f, 0.f, 0.f, 0.f);
            if (bn0 + r < N)
                v = *reinterpret_cast<const float4*>(
                    W + (size_t)(bn0 + r) * K + k0 + c4 * 4);
            Bs[c4 * 4 + 0][r] = v.x;
            Bs[c4 * 4 + 1][r] = v.y;
            Bs[c4 * 4 + 2][r] = v.z;
            Bs[c4 * 4 + 3][r] = v.w;
        }
        __syncthreads();

#pragma unroll
        for (int k = 0; k < 16; k++) {
            float4 a0 = *reinterpret_cast<const float4*>(&As[k][trow * 8]);
            float4 a1 = *reinterpret_cast<const float4*>(&As[k][trow * 8 + 4]);
            float4 bb = *reinterpret_cast<const float4*>(&Bs[k][tcol * 4]);
            float rA[8] = {a0.x, a0.y, a0.z, a0.w, a1.x, a1.y, a1.z, a1.w};
            float rB[4] = {bb.x, bb.y, bb.z, bb.w};
#pragma unroll
            for (int i = 0; i < 8; i++)
#pragma unroll
                for (int j = 0; j < 4; j++)
                    acc[i][j] += rA[i] * rB[j];
        }
        __syncthreads();
    }

#pragma unroll
    for (int i = 0; i < 8; i++) {
        int m = bm0 + trow * 8 + i;
#pragma unroll
        for (int j = 0; j < 4; j++) {
            int n = bn0 + tcol * 4 + j;
            if (n < N) {
                float v = acc[i][j];
                if (bias) v += bias[n];
                Y[(size_t)m * N + n] = v;
            }
        }
    }
}

// ---------------- RMSNorm: one warp per 512-wide row ----------------
__global__ __launch_bounds__(256) void rmsnorm_kernel(
    const float* __restrict__ X, const float* __restrict__ w,
    float* __restrict__ Y, int rows)
{
    int row  = blockIdx.x * 8 + (threadIdx.x >> 5);
    int lane = threadIdx.x & 31;
    if (row >= rows) return;
    const float* xp = X + (size_t)row * DIM;
    float x[16];
    float ss = 0.f;
#pragma unroll
    for (int t = 0; t < 16; t++) {
        x[t] = xp[lane + t * 32];
        ss += x[t] * x[t];
    }
#pragma unroll
    for (int o = 16; o > 0; o >>= 1) ss += __shfl_xor_sync(0xffffffffu, ss, o);
    float rs = rsqrtf(ss * (1.0f / 512.0f) + RMS_EPS);
    float* yp = Y + (size_t)row * DIM;
#pragma unroll
    for (int t = 0; t < 16; t++)
        yp[lane + t * 32] = x[t] * rs * w[lane + t * 32];
}

// ---------------- Self attention (n=256, online softmax, NO scale) ----------------
// grid: (HEADS, 12 batches), block 256 threads = one thread per query row.
__global__ __launch_bounds__(256) void self_attn_kernel(
    const float* __restrict__ Q, const float* __restrict__ KV,
    float* __restrict__ O)
{
    const int h     = blockIdx.x;
    const int batch = blockIdx.y;
    const int i     = threadIdx.x;

    __shared__ float Ks[64][64];
    __shared__ float Vs[64][64];

    float q[64];
    {
        const float* qp = Q + ((size_t)(batch * 256 + i)) * 512 + h * 64;
#pragma unroll
        for (int t = 0; t < 16; t++) {
            float4 v = *reinterpret_cast<const float4*>(qp + t * 4);
            q[4 * t + 0] = v.x; q[4 * t + 1] = v.y;
            q[4 * t + 2] = v.z; q[4 * t + 3] = v.w;
        }
    }

    float m = -1e30f, l = 0.f;
    float acc[64];
#pragma unroll
    for (int t = 0; t < 64; t++) acc[t] = 0.f;

    for (int j0 = 0; j0 < 256; j0 += 64) {
        __syncthreads();
#pragma unroll
        for (int s = 0; s < 4; s++) {
            int u  = threadIdx.x + s * 256;
            int jr = u >> 4;
            int c4 = u & 15;
            const float* kp = KV + ((size_t)(batch * 256 + j0 + jr)) * 1024 + h * 64 + c4 * 4;
            *reinterpret_cast<float4*>(&Ks[jr][c4 * 4]) = *reinterpret_cast<const float4*>(kp);
            *reinterpret_cast<float4*>(&Vs[jr][c4 * 4]) = *reinterpret_cast<const float4*>(kp + 512);
        }
        __syncthreads();

        for (int j = 0; j < 64; j++) {
            const float4* kr = reinterpret_cast<const float4*>(Ks[j]);
            float s = 0.f;
#pragma unroll
            for (int t = 0; t < 16; t++) {
                float4 kk = kr[t];
                s += q[4 * t + 0] * kk.x + q[4 * t + 1] * kk.y
                   + q[4 * t + 2] * kk.z + q[4 * t + 3] * kk.w;
            }
            float mn = fmaxf(m, s);
            float f  = __expf(m - mn);
            float p  = __expf(s - mn);
            l = l * f + p;
            const float4* vr = reinterpret_cast<const float4*>(Vs[j]);
#pragma unroll
            for (int t = 0; t < 16; t++) {
                float4 vv = vr[t];
                acc[4 * t + 0] = acc[4 * t + 0] * f + p * vv.x;
                acc[4 * t + 1] = acc[4 * t + 1] * f + p * vv.y;
                acc[4 * t + 2] = acc[4 * t + 2] * f + p * vv.z;
                acc[4 * t + 3] = acc[4 * t + 3] * f + p * vv.w;
            }
            m = mn;
        }
    }

    float inv = 1.0f / l;
    float* op = O + ((size_t)(batch * 256 + i)) * 512 + h * 64;
#pragma unroll
    for (int t = 0; t < 16; t++) {
        float4 v;
        v.x = acc[4 * t + 0] * inv; v.y = acc[4 * t + 1] * inv;
        v.z = acc[4 * t + 2] * inv; v.w = acc[4 * t + 3] * inv;
        *reinterpret_cast<float4*>(op + t * 4) = v;
    }
}

// ---------------- Residual attention: one block per query (3072), warp = head ----
__global__ __launch_bounds__(256) void res_attn_kernel(
    const float* __restrict__ Qr, const float* __restrict__ KVM,
    float* __restrict__ Or, int M)
{
    const int r     = blockIdx.x;         // (block*2+b)*256+n
    const int block = r >> 9;
    const int bq    = (r >> 8) & 1;
    const int n     = r & 255;
    const int c     = 2 * block + bq;
    const int bprime = c / 6;             // einops (b blocks) vs (blocks b) quirk

    const int tid  = threadIdx.x;
    const int h    = tid >> 5;
    const int lane = tid & 31;

    __shared__ float qs[512];
    __shared__ float sim[8][64];

    qs[tid]       = Qr[(size_t)r * 512 + tid];
    qs[tid + 256] = Qr[(size_t)r * 512 + tid + 256];
    __syncthreads();

    // scores for this head
    for (int mi = lane; mi < M; mi += 32) {
        const float4* k4 = reinterpret_cast<const float4*>(
            KVM + ((size_t)((mi * 2 + bprime) * 256 + n)) * 1024 + h * 64);
        const float4* q4 = reinterpret_cast<const float4*>(&qs[h * 64]);
        float s = 0.f;
#pragma unroll
        for (int t = 0; t < 16; t++) {
            float4 kk = k4[t];
            float4 qq = q4[t];
            s += qq.x * kk.x + qq.y * kk.y + qq.z * kk.z + qq.w * kk.w;
        }
        sim[h][mi] = s;
    }
    __syncwarp();

    // softmax over m (M <= 42)
    float v0 = (lane < M)      ? sim[h][lane]      : -1e30f;
    float v1 = (lane + 32 < M) ? sim[h][lane + 32] : -1e30f;
    float mx = fmaxf(v0, v1);
#pragma unroll
    for (int o = 16; o > 0; o >>= 1) mx = fmaxf(mx, __shfl_xor_sync(0xffffffffu, mx, o));
    float p0 = (lane < M)      ? __expf(v0 - mx) : 0.f;
    float p1 = (lane + 32 < M) ? __expf(v1 - mx) : 0.f;
    if (lane < M)      sim[h][lane]      = p0;
    if (lane + 32 < M) sim[h][lane + 32] = p1;
    float ls = p0 + p1;
#pragma unroll
    for (int o = 16; o > 0; o >>= 1) ls += __shfl_xor_sync(0xffffffffu, ls, o);
    __syncwarp();

    // out: each lane covers dh = lane, lane+32
    float o0 = 0.f, o1 = 0.f;
    for (int mi = 0; mi < M; mi++) {
        float a = sim[h][mi];
        const float* vp = KVM + ((size_t)((mi * 2 + bprime) * 256 + n)) * 1024 + 512 + h * 64;
        o0 += a * vp[lane];
        o1 += a * vp[lane + 32];
    }
    float inv = 1.0f / ls;
    Or[(size_t)r * 512 + h * 64 + lane]      = o0 * inv;
    Or[(size_t)r * 512 + h * 64 + lane + 32] = o1 * inv;
}

// ---------------- GEGLU (exact erf gelu), writes zero-padded ACT --------------
__global__ void geglu_kernel(const float* __restrict__ H, float* __restrict__ A)
{
    int idx = blockIdx.x * blockDim.x + threadIdx.x;
    if (idx >= ROWS * DFFP) return;
    int row = idx / DFFP;
    int e   = idx - row * DFFP;
    float out = 0.f;
    if (e < DFF) {
        float s = H[(size_t)row * DFF2 + e];
        float g = H[(size_t)row * DFF2 + DFF + e];
        out = s * (0.5f * g * (1.0f + erff(g * 0.70710678118654752440f)));
    }
    A[idx] = out;
}

// ---------------- init: broadcast tokens into T and msg[0..5] -----------------
__global__ void init_bcast_kernel(const float* __restrict__ tokens,
                                  float* __restrict__ T, float* __restrict__ msg)
{
    int idx = blockIdx.x * blockDim.x + threadIdx.x;
    if (idx >= ROWS * DIM) return;
    int dd = idx & 511;
    int rr = idx >> 9;            // (block*2+b)*256+n
    int n  = rr & 255;
    int b  = (rr >> 8) & 1;
    float v = tokens[((size_t)(b * 256 + n)) * 512 + dd];
    T[idx]   = v;
    msg[idx] = v;
}

// ---------------- pad ff_values_w [512,1365] -> [512,1376] --------------------
__global__ void pad_w_kernel(const float* __restrict__ W, float* __restrict__ Wp)
{
    int idx = blockIdx.x * blockDim.x + threadIdx.x;
    if (idx >= DIM * DFFP) return;
    int row = idx / DFFP;
    int col = idx - row * DFFP;
    Wp[idx] = (col < DFF) ? W[(size_t)row * DFF + col] : 0.f;
}

// -------------------------------- launch --------------------------------------
extern "C" void kernel_launch(void* const* d_in, const int* in_sizes, int n_in,
                              void* d_out, int out_size)
{
    const float* tokens      = (const float*)d_in[0];
    const float* attn_norm_w = (const float*)d_in[1];
    const float* attn_wq     = (const float*)d_in[2];
    const float* attn_wkv    = (const float*)d_in[3];
    const float* attn_wo     = (const float*)d_in[4];
    const float* ff_norm_w   = (const float*)d_in[5];
    const float* ff_keys_w   = (const float*)d_in[6];
    const float* ff_keys_b   = (const float*)d_in[7];
    const float* ff_values_w = (const float*)d_in[8];
    const float* ff_values_b = (const float*)d_in[9];
    const float* res_norm_w  = (const float*)d_in[10];
    const float* res_wq      = (const float*)d_in[11];
    const float* res_wkv     = (const float*)d_in[12];
    const float* res_wo      = (const float*)d_in[13];
    float* out = (float*)d_out;

    float *T, *XN, *Q, *KV, *O, *H, *ACT, *Or, *msg, *kvm, *Wvp;
    cudaGetSymbolAddress((void**)&T,   g_T);
    cudaGetSymbolAddress((void**)&XN,  g_XN);
    cudaGetSymbolAddress((void**)&Q,   g_Q);
    cudaGetSymbolAddress((void**)&KV,  g_KV);
    cudaGetSymbolAddress((void**)&O,   g_O);
    cudaGetSymbolAddress((void**)&H,   g_H);
    cudaGetSymbolAddress((void**)&ACT, g_ACT);
    cudaGetSymbolAddress((void**)&Or,  g_Or);
    cudaGetSymbolAddress((void**)&msg, g_msg);
    cudaGetSymbolAddress((void**)&kvm, g_kvm);
    cudaGetSymbolAddress((void**)&Wvp, g_Wvp);

    init_bcast_kernel<<<(ROWS * DIM + 255) / 256, 256>>>(tokens, T, msg);
    pad_w_kernel<<<(DIM * DFFP + 255) / 256, 256>>>(ff_values_w, Wvp);

    int Mtot = 6;
    for (int e = 0; e < 3; e++) {
        // ---- self attention over the 12 flattened sequences ----
        rmsnorm_kernel<<<ROWS / 8, 256>>>(T, attn_norm_w, XN, ROWS);
        sgemm_nt<<<dim3(8, 24), 256>>>(XN, 512, attn_wq,  nullptr, Q,  ROWS, 512, 512);
        sgemm_nt<<<dim3(16, 24), 256>>>(T,  512, attn_wkv, nullptr, KV, ROWS, 1024, 512);
        self_attn_kernel<<<dim3(HEADS, 12), 256>>>(Q, KV, O);
        float* att_dst = msg + (size_t)Mtot * 512 * DIM;
        sgemm_nt<<<dim3(8, 24), 256>>>(O, 512, attn_wo, nullptr, att_dst, ROWS, 512, 512);

        // ---- feedforward (geglu, exact gelu) ----
        rmsnorm_kernel<<<ROWS / 8, 256>>>(T, ff_norm_w, XN, ROWS);
        sgemm_nt<<<dim3((DFF2 + 63) / 64, 24), 256>>>(XN, 512, ff_keys_w, ff_keys_b, H, ROWS, DFF2, 512);
        geglu_kernel<<<(ROWS * DFFP + 255) / 256, 256>>>(H, ACT);
        float* ret_dst = msg + (size_t)(Mtot + 6) * 512 * DIM;
        sgemm_nt<<<dim3(8, 24), 256>>>(ACT, DFFP, Wvp, ff_values_b, ret_dst, ROWS, 512, DFFP);

        int Mnew = Mtot + 12;

        // ---- KV projection for NEW message slabs only (cached across exchanges) ----
        int startm = (e == 0) ? 0 : Mtot;       // include the 6 initial token slabs once
        int nrows  = (Mnew - startm) * 512;
        sgemm_nt<<<dim3(16, nrows / 128), 256>>>(
            msg + (size_t)startm * 512 * DIM, 512, res_wkv, nullptr,
            kvm + (size_t)startm * 512 * 1024, nrows, 1024, 512);
        Mtot = Mnew;

        // ---- residual pooled attention (1 query over Mtot messages) ----
        rmsnorm_kernel<<<ROWS / 8, 256>>>(T, res_norm_w, XN, ROWS);
        sgemm_nt<<<dim3(8, 24), 256>>>(XN, 512, res_wq, nullptr, Q, ROWS, 512, 512);
        res_attn_kernel<<<ROWS, 256>>>(Q, kvm, Or, Mtot);
        float* tdst = (e == 2) ? out : T;
        sgemm_nt<<<dim3(8, 24), 256>>>(Or, 512, res_wo, nullptr, tdst, ROWS, 512, 512);
    }
}

// round 2
// speedup vs baseline: 1.0943x; 1.0943x over previous
#include <cuda_runtime.h>
#include <math.h>

#define DIM     512
#define NTOK    256
#define NB      2
#define NBLK    6
#define HEADS   8
#define DHEAD   64
#define DFF     1365
#define DFF2    2730
#define DFFP    1376        // DFF padded to multiple of 16
#define MAXM    42
#define ROWS    3072        // NBLK*NB*NTOK
#define RMS_EPS 1.1920929e-07f

// ---------------- scratch (device globals; no runtime allocation) ----------------
static __device__ float g_T   [ROWS * DIM];
static __device__ float g_XN  [ROWS * DIM];
static __device__ float g_Q   [ROWS * DIM];
static __device__ float g_KV  [ROWS * 1024];
static __device__ float g_O   [ROWS * DIM];
static __device__ float g_H   [ROWS * DFF2];
static __device__ float g_ACT [ROWS * DFFP];
static __device__ float g_Or  [ROWS * DIM];
static __device__ float g_msg [(size_t)MAXM * 512 * DIM];    // row = (m*2+b)*256+n
static __device__ float g_kvm [(size_t)MAXM * 512 * 1024];   // same row layout, 1024 cols
static __device__ float g_Wvp [DIM * DFFP];                  // padded ff_values_w

// ---------------- packed f32x2 helpers (sm_103a FFMA2 path) ----------------
__device__ __forceinline__ void ffma2(unsigned long long& d,
                                      unsigned long long a,
                                      unsigned long long b) {
    asm("fma.rn.f32x2 %0, %1, %2, %0;" : "+l"(d) : "l"(a), "l"(b));
}
__device__ __forceinline__ unsigned long long fma2_3(unsigned long long a,
                                                     unsigned long long b,
                                                     unsigned long long c) {
    unsigned long long d;
    asm("fma.rn.f32x2 %0, %1, %2, %3;" : "=l"(d) : "l"(a), "l"(b), "l"(c));
    return d;
}
__device__ __forceinline__ unsigned long long mul2(unsigned long long a,
                                                   unsigned long long b) {
    unsigned long long d;
    asm("mul.rn.f32x2 %0, %1, %2;" : "=l"(d) : "l"(a), "l"(b));
    return d;
}
__device__ __forceinline__ unsigned long long dup2(float x) {
    unsigned long long r;
    asm("mov.b64 %0, {%1, %1};" : "=l"(r) : "f"(x));
    return r;
}
__device__ __forceinline__ unsigned long long pk2(float x, float y) {
    unsigned long long r;
    asm("mov.b64 %0, {%1, %2};" : "=l"(r) : "f"(x), "f"(y));
    return r;
}
__device__ __forceinline__ float2 unpack2(unsigned long long v) {
    float2 f;
    asm("mov.b64 {%0, %1}, %2;" : "=f"(f.x), "=f"(f.y) : "l"(v));
    return f;
}

// ---------------- SGEMM:  Y[m,n] = sum_k X[m,k]*W[n,k] (+bias[n]) ----------------
// BM=128, BN=64, BK=16, 256 threads, each thread 8x4 (FFMA2-packed along m).
// Double-buffered smem. Requirements: M%128==0, K%16==0, lda%4==0, W stride==K.
__global__ __launch_bounds__(256, 2) void sgemm_nt(
    const float* __restrict__ X, int lda,
    const float* __restrict__ W,
    const float* __restrict__ bias,
    float* __restrict__ Y,
    int M, int N, int K)
{
    __shared__ __align__(16) float As[2][16][132];
    __shared__ __align__(16) float Bs[2][16][68];

    const int tid  = threadIdx.x;
    const int bm0  = blockIdx.y * 128;
    const int bn0  = blockIdx.x * 64;
    const int trow = tid >> 4;        // 0..15 -> m offset trow*8
    const int tcol = tid & 15;        // 0..15 -> n offset tcol*4
    const int lr   = tid >> 2;        // 0..63 loader row
    const int lc4  = (tid & 3) * 4;   // 0,4,8,12 loader k

    unsigned long long acc[4][4];
#pragma unroll
    for (int i = 0; i < 4; i++)
#pragma unroll
        for (int j = 0; j < 4; j++) acc[i][j] = 0ull;

    const float* Xp0 = X + (size_t)(bm0 + lr)      * lda + lc4;
    const float* Xp1 = X + (size_t)(bm0 + lr + 64) * lda + lc4;
    const float* Wp  = W + (size_t)(bn0 + lr) * K + lc4;
    const bool   wok = (bn0 + lr) < N;

    float4 xv0, xv1, wv;
    // prologue: load k-tile 0
    xv0 = *reinterpret_cast<const float4*>(Xp0);
    xv1 = *reinterpret_cast<const float4*>(Xp1);
    wv  = wok ? *reinterpret_cast<const float4*>(Wp) : make_float4(0.f, 0.f, 0.f, 0.f);
    As[0][lc4 + 0][lr]      = xv0.x; As[0][lc4 + 1][lr]      = xv0.y;
    As[0][lc4 + 2][lr]      = xv0.z; As[0][lc4 + 3][lr]      = xv0.w;
    As[0][lc4 + 0][lr + 64] = xv1.x; As[0][lc4 + 1][lr + 64] = xv1.y;
    As[0][lc4 + 2][lr + 64] = xv1.z; As[0][lc4 + 3][lr + 64] = xv1.w;
    Bs[0][lc4 + 0][lr] = wv.x; Bs[0][lc4 + 1][lr] = wv.y;
    Bs[0][lc4 + 2][lr] = wv.z; Bs[0][lc4 + 3][lr] = wv.w;
    __syncthreads();

    const int nk = K >> 4;
    for (int t = 0; t < nk; t++) {
        const int buf = t & 1;
        if (t + 1 < nk) {
            const int ko = (t + 1) * 16;
            xv0 = *reinterpret_cast<const float4*>(Xp0 + ko);
            xv1 = *reinterpret_cast<const float4*>(Xp1 + ko);
            wv  = wok ? *reinterpret_cast<const float4*>(Wp + ko)
                      : make_float4(0.f, 0.f, 0.f, 0.f);
        }
#pragma unroll
        for (int k = 0; k < 16; k++) {
            ulonglong2 A0 = *reinterpret_cast<const ulonglong2*>(&As[buf][k][trow * 8]);
            ulonglong2 A1 = *reinterpret_cast<const ulonglong2*>(&As[buf][k][trow * 8 + 4]);
            float4 b4 = *reinterpret_cast<const float4*>(&Bs[buf][k][tcol * 4]);
            unsigned long long b0 = dup2(b4.x), b1 = dup2(b4.y),
                               b2 = dup2(b4.z), b3 = dup2(b4.w);
            ffma2(acc[0][0], A0.x, b0); ffma2(acc[0][1], A0.x, b1);
            ffma2(acc[0][2], A0.x, b2); ffma2(acc[0][3], A0.x, b3);
            ffma2(acc[1][0], A0.y, b0); ffma2(acc[1][1], A0.y, b1);
            ffma2(acc[1][2], A0.y, b2); ffma2(acc[1][3], A0.y, b3);
            ffma2(acc[2][0], A1.x, b0); ffma2(acc[2][1], A1.x, b1);
            ffma2(acc[2][2], A1.x, b2); ffma2(acc[2][3], A1.x, b3);
            ffma2(acc[3][0], A1.y, b0); ffma2(acc[3][1], A1.y, b1);
            ffma2(acc[3][2], A1.y, b2); ffma2(acc[3][3], A1.y, b3);
        }
        if (t + 1 < nk) {
            const int nb = buf ^ 1;
            As[nb][lc4 + 0][lr]      = xv0.x; As[nb][lc4 + 1][lr]      = xv0.y;
            As[nb][lc4 + 2][lr]      = xv0.z; As[nb][lc4 + 3][lr]      = xv0.w;
            As[nb][lc4 + 0][lr + 64] = xv1.x; As[nb][lc4 + 1][lr + 64] = xv1.y;
            As[nb][lc4 + 2][lr + 64] = xv1.z; As[nb][lc4 + 3][lr + 64] = xv1.w;
            Bs[nb][lc4 + 0][lr] = wv.x; Bs[nb][lc4 + 1][lr] = wv.y;
            Bs[nb][lc4 + 2][lr] = wv.z; Bs[nb][lc4 + 3][lr] = wv.w;
        }
        __syncthreads();
    }

#pragma unroll
    for (int i2 = 0; i2 < 4; i2++) {
        const int m = bm0 + trow * 8 + i2 * 2;
#pragma unroll
        for (int j = 0; j < 4; j++) {
            const int n = bn0 + tcol * 4 + j;
            if (n < N) {
                float2 v = unpack2(acc[i2][j]);
                float bb = bias ? bias[n] : 0.f;
                Y[(size_t)m * N + n]       = v.x + bb;
                Y[(size_t)(m + 1) * N + n] = v.y + bb;
            }
        }
    }
}

// ---------------- RMSNorm: one warp per 512-wide row ----------------
__global__ __launch_bounds__(256) void rmsnorm_kernel(
    const float* __restrict__ X, const float* __restrict__ w,
    float* __restrict__ Y, int rows)
{
    int row  = blockIdx.x * 8 + (threadIdx.x >> 5);
    int lane = threadIdx.x & 31;
    if (row >= rows) return;
    const float* xp = X + (size_t)row * DIM;
    float x[16];
    float ss = 0.f;
#pragma unroll
    for (int t = 0; t < 16; t++) {
        x[t] = xp[lane + t * 32];
        ss += x[t] * x[t];
    }
#pragma unroll
    for (int o = 16; o > 0; o >>= 1) ss += __shfl_xor_sync(0xffffffffu, ss, o);
    float rs = rsqrtf(ss * (1.0f / 512.0f) + RMS_EPS);
    float* yp = Y + (size_t)row * DIM;
#pragma unroll
    for (int t = 0; t < 16; t++)
        yp[lane + t * 32] = x[t] * rs * w[lane + t * 32];
}

// ---------------- Self attention (n=256, online softmax, NO scale) ----------------
// grid: (HEADS, 12 batches), block 256 threads = one thread per query row.
__global__ __launch_bounds__(256) void self_attn_kernel(
    const float* __restrict__ Q, const float* __restrict__ KV,
    float* __restrict__ O)
{
    const int h     = blockIdx.x;
    const int batch = blockIdx.y;
    const int i     = threadIdx.x;

    __shared__ __align__(16) float Ks[64][64];
    __shared__ __align__(16) float Vs[64][64];

    unsigned long long qp[32];
    {
        const float4* qq = reinterpret_cast<const float4*>(
            Q + ((size_t)(batch * 256 + i)) * 512 + h * 64);
#pragma unroll
        for (int t = 0; t < 16; t++) {
            float4 v = qq[t];
            qp[2 * t]     = pk2(v.x, v.y);
            qp[2 * t + 1] = pk2(v.z, v.w);
        }
    }

    float m = -1e30f, l = 0.f;
    unsigned long long acc[32];
#pragma unroll
    for (int t = 0; t < 32; t++) acc[t] = 0ull;

    for (int j0 = 0; j0 < 256; j0 += 64) {
        __syncthreads();
#pragma unroll
        for (int s = 0; s < 4; s++) {
            int u  = threadIdx.x + s * 256;
            int jr = u >> 4;
            int c4 = u & 15;
            const float* kp = KV + ((size_t)(batch * 256 + j0 + jr)) * 1024 + h * 64 + c4 * 4;
            *reinterpret_cast<float4*>(&Ks[jr][c4 * 4]) = *reinterpret_cast<const float4*>(kp);
            *reinterpret_cast<float4*>(&Vs[jr][c4 * 4]) = *reinterpret_cast<const float4*>(kp + 512);
        }
        __syncthreads();

        for (int j = 0; j < 64; j++) {
            const ulonglong2* kr = reinterpret_cast<const ulonglong2*>(Ks[j]);
            unsigned long long s0 = 0ull, s1 = 0ull;
#pragma unroll
            for (int t = 0; t < 8; t++) {
                ulonglong2 k0 = kr[2 * t];
                ulonglong2 k1 = kr[2 * t + 1];
                ffma2(s0, qp[4 * t + 0], k0.x);
                ffma2(s1, qp[4 * t + 1], k0.y);
                ffma2(s0, qp[4 * t + 2], k1.x);
                ffma2(s1, qp[4 * t + 3], k1.y);
            }
            float2 sa = unpack2(s0), sb = unpack2(s1);
            float s = (sa.x + sa.y) + (sb.x + sb.y);

            float mn = fmaxf(m, s);
            float f  = __expf(m - mn);
            float p  = __expf(s - mn);
            l = l * f + p;
            unsigned long long fd = dup2(f), pd = dup2(p);
            const ulonglong2* vr = reinterpret_cast<const ulonglong2*>(Vs[j]);
#pragma unroll
            for (int t = 0; t < 16; t++) {
                ulonglong2 vv = vr[t];
                acc[2 * t]     = fma2_3(acc[2 * t],     fd, mul2(vv.x, pd));
                acc[2 * t + 1] = fma2_3(acc[2 * t + 1], fd, mul2(vv.y, pd));
            }
            m = mn;
        }
    }

    float inv = 1.0f / l;
    float* op = O + ((size_t)(batch * 256 + i)) * 512 + h * 64;
#pragma unroll
    for (int t = 0; t < 16; t++) {
        float2 a = unpack2(acc[2 * t]);
        float2 b = unpack2(acc[2 * t + 1]);
        float4 v;
        v.x = a.x * inv; v.y = a.y * inv;
        v.z = b.x * inv; v.w = b.y * inv;
        *reinterpret_cast<float4*>(op + t * 4) = v;
    }
}

// ---------------- Residual attention: one block per query (3072), warp = head ----
__global__ __launch_bounds__(256) void res_attn_kernel(
    const float* __restrict__ Qr, const float* __restrict__ KVM,
    float* __restrict__ Or, int M)
{
    const int r     = blockIdx.x;         // (block*2+b)*256+n
    const int block = r >> 9;
    const int bq    = (r >> 8) & 1;
    const int n     = r & 255;
    const int c     = 2 * block + bq;
    const int bprime = c / 6;             // einops (b blocks) vs (blocks b) quirk

    const int tid  = threadIdx.x;
    const int h    = tid >> 5;
    const int lane = tid & 31;

    __shared__ float qs[512];
    __shared__ float sim[8][64];

    qs[tid]       = Qr[(size_t)r * 512 + tid];
    qs[tid + 256] = Qr[(size_t)r * 512 + tid + 256];
    __syncthreads();

    // scores for this head
    for (int mi = lane; mi < M; mi += 32) {
        const float4* k4 = reinterpret_cast<const float4*>(
            KVM + ((size_t)((mi * 2 + bprime) * 256 + n)) * 1024 + h * 64);
        const float4* q4 = reinterpret_cast<const float4*>(&qs[h * 64]);
        float s = 0.f;
#pragma unroll
        for (int t = 0; t < 16; t++) {
            float4 kk = k4[t];
            float4 qq = q4[t];
            s += qq.x * kk.x + qq.y * kk.y + qq.z * kk.z + qq.w * kk.w;
        }
        sim[h][mi] = s;
    }
    __syncwarp();

    // softmax over m (M <= 42)
    float v0 = (lane < M)      ? sim[h][lane]      : -1e30f;
    float v1 = (lane + 32 < M) ? sim[h][lane + 32] : -1e30f;
    float mx = fmaxf(v0, v1);
#pragma unroll
    for (int o = 16; o > 0; o >>= 1) mx = fmaxf(mx, __shfl_xor_sync(0xffffffffu, mx, o));
    float p0 = (lane < M)      ? __expf(v0 - mx) : 0.f;
    float p1 = (lane + 32 < M) ? __expf(v1 - mx) : 0.f;
    if (lane < M)      sim[h][lane]      = p0;
    if (lane + 32 < M) sim[h][lane + 32] = p1;
    float ls = p0 + p1;
#pragma unroll
    for (int o = 16; o > 0; o >>= 1) ls += __shfl_xor_sync(0xffffffffu, ls, o);
    __syncwarp();

    // out: each lane covers dh = lane, lane+32
    float o0 = 0.f, o1 = 0.f;
    for (int mi = 0; mi < M; mi++) {
        float a = sim[h][mi];
        const float* vp = KVM + ((size_t)((mi * 2 + bprime) * 256 + n)) * 1024 + 512 + h * 64;
        o0 += a * vp[lane];
        o1 += a * vp[lane + 32];
    }
    float inv = 1.0f / ls;
    Or[(size_t)r * 512 + h * 64 + lane]      = o0 * inv;
    Or[(size_t)r * 512 + h * 64 + lane + 32] = o1 * inv;
}

// ---------------- GEGLU (exact erf gelu), writes zero-padded ACT --------------
__global__ void geglu_kernel(const float* __restrict__ H, float* __restrict__ A)
{
    int idx = blockIdx.x * blockDim.x + threadIdx.x;
    if (idx >= ROWS * DFFP) return;
    int row = idx / DFFP;
    int e   = idx - row * DFFP;
    float out = 0.f;
    if (e < DFF) {
        float s = H[(size_t)row * DFF2 + e];
        float g = H[(size_t)row * DFF2 + DFF + e];
        out = s * (0.5f * g * (1.0f + erff(g * 0.70710678118654752440f)));
    }
    A[idx] = out;
}

// ---------------- init: broadcast tokens into T and msg[0..5] -----------------
__global__ void init_bcast_kernel(const float* __restrict__ tokens,
                                  float* __restrict__ T, float* __restrict__ msg)
{
    int idx = blockIdx.x * blockDim.x + threadIdx.x;
    if (idx >= ROWS * DIM) return;
    int dd = idx & 511;
    int rr = idx >> 9;            // (block*2+b)*256+n
    int n  = rr & 255;
    int b  = (rr >> 8) & 1;
    float v = tokens[((size_t)(b * 256 + n)) * 512 + dd];
    T[idx]   = v;
    msg[idx] = v;
}

// ---------------- pad ff_values_w [512,1365] -> [512,1376] --------------------
__global__ void pad_w_kernel(const float* __restrict__ W, float* __restrict__ Wp)
{
    int idx = blockIdx.x * blockDim.x + threadIdx.x;
    if (idx >= DIM * DFFP) return;
    int row = idx / DFFP;
    int col = idx - row * DFFP;
    Wp[idx] = (col < DFF) ? W[(size_t)row * DFF + col] : 0.f;
}

// -------------------------------- launch --------------------------------------
extern "C" void kernel_launch(void* const* d_in, const int* in_sizes, int n_in,
                              void* d_out, int out_size)
{
    const float* tokens      = (const float*)d_in[0];
    const float* attn_norm_w = (const float*)d_in[1];
    const float* attn_wq     = (const float*)d_in[2];
    const float* attn_wkv    = (const float*)d_in[3];
    const float* attn_wo     = (const float*)d_in[4];
    const float* ff_norm_w   = (const float*)d_in[5];
    const float* ff_keys_w   = (const float*)d_in[6];
    const float* ff_keys_b   = (const float*)d_in[7];
    const float* ff_values_w = (const float*)d_in[8];
    const float* ff_values_b = (const float*)d_in[9];
    const float* res_norm_w  = (const float*)d_in[10];
    const float* res_wq      = (const float*)d_in[11];
    const float* res_wkv     = (const float*)d_in[12];
    const float* res_wo      = (const float*)d_in[13];
    float* out = (float*)d_out;

    float *T, *XN, *Q, *KV, *O, *H, *ACT, *Or, *msg, *kvm, *Wvp;
    cudaGetSymbolAddress((void**)&T,   g_T);
    cudaGetSymbolAddress((void**)&XN,  g_XN);
    cudaGetSymbolAddress((void**)&Q,   g_Q);
    cudaGetSymbolAddress((void**)&KV,  g_KV);
    cudaGetSymbolAddress((void**)&O,   g_O);
    cudaGetSymbolAddress((void**)&H,   g_H);
    cudaGetSymbolAddress((void**)&ACT, g_ACT);
    cudaGetSymbolAddress((void**)&Or,  g_Or);
    cudaGetSymbolAddress((void**)&msg, g_msg);
    cudaGetSymbolAddress((void**)&kvm, g_kvm);
    cudaGetSymbolAddress((void**)&Wvp, g_Wvp);

    init_bcast_kernel<<<(ROWS * DIM + 255) / 256, 256>>>(tokens, T, msg);
    pad_w_kernel<<<(DIM * DFFP + 255) / 256, 256>>>(ff_values_w, Wvp);

    int Mtot = 6;
    for (int e = 0; e < 3; e++) {
        // ---- self attention over the 12 flattened sequences ----
        rmsnorm_kernel<<<ROWS / 8, 256>>>(T, attn_norm_w, XN, ROWS);
        sgemm_nt<<<dim3(8, 24), 256>>>(XN, 512, attn_wq,  nullptr, Q,  ROWS, 512, 512);
        sgemm_nt<<<dim3(16, 24), 256>>>(T,  512, attn_wkv, nullptr, KV, ROWS, 1024, 512);
        self_attn_kernel<<<dim3(HEADS, 12), 256>>>(Q, KV, O);
        float* att_dst = msg + (size_t)Mtot * 512 * DIM;
        sgemm_nt<<<dim3(8, 24), 256>>>(O, 512, attn_wo, nullptr, att_dst, ROWS, 512, 512);

        // ---- feedforward (geglu, exact gelu) ----
        rmsnorm_kernel<<<ROWS / 8, 256>>>(T, ff_norm_w, XN, ROWS);
        sgemm_nt<<<dim3((DFF2 + 63) / 64, 24), 256>>>(XN, 512, ff_keys_w, ff_keys_b, H, ROWS, DFF2, 512);
        geglu_kernel<<<(ROWS * DFFP + 255) / 256, 256>>>(H, ACT);
        float* ret_dst = msg + (size_t)(Mtot + 6) * 512 * DIM;
        sgemm_nt<<<dim3(8, 24), 256>>>(ACT, DFFP, Wvp, ff_values_b, ret_dst, ROWS, 512, DFFP);

        int Mnew = Mtot + 12;

        // ---- KV projection for NEW message slabs only (cached across exchanges) ----
        int startm = (e == 0) ? 0 : Mtot;       // include the 6 initial token slabs once
        int nrows  = (Mnew - startm) * 512;
        sgemm_nt<<<dim3(16, nrows / 128), 256>>>(
            msg + (size_t)startm * 512 * DIM, 512, res_wkv, nullptr,
            kvm + (size_t)startm * 512 * 1024, nrows, 1024, 512);
        Mtot = Mnew;

        // ---- residual pooled attention (1 query over Mtot messages) ----
        rmsnorm_kernel<<<ROWS / 8, 256>>>(T, res_norm_w, XN, ROWS);
        sgemm_nt<<<dim3(8, 24), 256>>>(XN, 512, res_wq, nullptr, Q, ROWS, 512, 512);
        res_attn_kernel<<<ROWS, 256>>>(Q, kvm, Or, Mtot);
        float* tdst = (e == 2) ? out : T;
        sgemm_nt<<<dim3(8, 24), 256>>>(Or, 512, res_wo, nullptr, tdst, ROWS, 512, 512);
    }
}